// round 15
// baseline (speedup 1.0000x reference)
#include <cuda_runtime.h>
#include <cuda_fp16.h>
#include <math.h>
#include <stdint.h>

#define NB 4
#define NT 2048
#define NDM 1024
#define NH 16
#define NDK 64

// fp16 staging buffers
__device__ __half g_xh[NB*NT*NDM];        // x in fp16            [b*t][d]
__device__ __half g_wth[3*NH*NDK*NDM];    // W fp16 transposed    [z*1024+n][d]
__device__ __half g_qh[NB*NH*NT*NDK];     // Q*0.125*log2e fp16   [bh][t][d]
__device__ __half g_kh[NB*NH*NT*NDK];     // K fp16               [bh][t][d]
__device__ __half g_vt[NB*NH*NDK*NT];     // V fp16 TRANSPOSED    [bh][d][t]

__device__ __forceinline__ void mma_f16(float* c, const uint32_t* a, const uint32_t* b) {
    asm volatile("mma.sync.aligned.m16n8k16.row.col.f32.f16.f16.f32 "
                 "{%0,%1,%2,%3}, {%4,%5,%6,%7}, {%8,%9}, {%0,%1,%2,%3};"
                 : "+f"(c[0]), "+f"(c[1]), "+f"(c[2]), "+f"(c[3])
                 : "r"(a[0]), "r"(a[1]), "r"(a[2]), "r"(a[3]),
                   "r"(b[0]), "r"(b[1]));
}
__device__ __forceinline__ void ldsm_x4(uint32_t* d, uint32_t addr) {
    asm volatile("ldmatrix.sync.aligned.m8n8.x4.shared.b16 {%0,%1,%2,%3}, [%4];"
                 : "=r"(d[0]), "=r"(d[1]), "=r"(d[2]), "=r"(d[3]) : "r"(addr));
}
__device__ __forceinline__ uint32_t smem_u32(const void* p) {
    uint32_t a;
    asm("{ .reg .u64 t; cvta.to.shared.u64 t, %1; cvt.u32.u64 %0, t; }"
        : "=r"(a) : "l"(p));
    return a;
}
__device__ __forceinline__ uint32_t h2e(float lo, float hi) {
    __half2 h = h2exp2(__floats2half2_rn(lo, hi));
    return *(uint32_t*)&h;
}
#define CP_ASYNC16(dst, src) \
    asm volatile("cp.async.cg.shared.global [%0], [%1], 16;" \
                 :: "r"(dst), "l"(src) : "memory")
#define CP_COMMIT  asm volatile("cp.async.commit_group;" ::: "memory")
#define CP_WAIT(n) asm volatile("cp.async.wait_group %0;" :: "n"(n) : "memory")

// ---------------------------------------------------------------------------
// Pre-pass 1: x -> fp16
// ---------------------------------------------------------------------------
__global__ __launch_bounds__(256) void convert_x(const float* __restrict__ x)
{
    const int i = ((int)blockIdx.x * 256 + (int)threadIdx.x) * 4;
    float4 v = *(const float4*)&x[i];
    *(__half2*)&g_xh[i]     = __floats2half2_rn(v.x, v.y);
    *(__half2*)&g_xh[i + 2] = __floats2half2_rn(v.z, v.w);
}

// ---------------------------------------------------------------------------
// Pre-pass 2: W[h][d][n] -> Wt fp16 [z*1024 + h*64 + n][d]
// ---------------------------------------------------------------------------
__global__ __launch_bounds__(256) void convert_w(
    const float* __restrict__ Wq, const float* __restrict__ Wk,
    const float* __restrict__ Wv)
{
    __shared__ float tile[32][33];
    const int zh = blockIdx.z;
    const int z = zh >> 4, h = zh & 15;
    const float* W = (z == 0 ? Wq : z == 1 ? Wk : Wv) + (size_t)h * NDM * NDK;
    const int d0 = blockIdx.x * 32;
    const int n0 = blockIdx.y * 32;
    const int tx = threadIdx.x, ty = threadIdx.y;

    #pragma unroll
    for (int j = 0; j < 4; j++)
        tile[ty + j * 8][tx] = W[(size_t)(d0 + ty + j * 8) * NDK + n0 + tx];
    __syncthreads();
    __half* dst = g_wth + ((size_t)(z * NH + h) * NDK) * NDM;
    #pragma unroll
    for (int j = 0; j < 4; j++)
        dst[(size_t)(n0 + ty + j * 8) * NDM + d0 + tx] =
            __float2half_rn(tile[tx][ty + j * 8]);
}

// ---------------------------------------------------------------------------
// Projection GEMM (round-13 v3, best measured): 128 threads, 4 warps (2x2),
// warp tile 64x64 (4mi x 8ni), BK=64 double-buffered.
// ---------------------------------------------------------------------------
#define PJ_STRIDE 72
#define PJ_TILE   (128 * PJ_STRIDE)
#define PJ_STAGE  (2 * PJ_TILE)
#define PJ_SMEM   (2 * PJ_STAGE * 2)     // 73728 B
#define VST 136

__global__ __launch_bounds__(128, 2) void proj_h()
{
    extern __shared__ __half smh[];
    const uint32_t smb = smem_u32(smh);

    const int m0 = blockIdx.x * 128;
    const int by = blockIdx.y;
    const int z  = by >> 3;
    const int n0 = (by & 7) * 128;
    const __half* wt = g_wth + (size_t)(z * 1024 + n0) * NDM;

    const int tid  = threadIdx.x;
    const int lane = tid & 31;
    const int qr   = lane >> 2;
    const int qc   = lane & 3;
    const int wid  = tid >> 5;
    const int wr   = wid >> 1;
    const int wc   = wid & 1;

    const int ch_  = (tid & 7) * 8;

    const uint32_t aoff = (uint32_t)(((wr * 64 + (lane & 15)) * PJ_STRIDE
                                      + (lane >> 4) * 8) * 2);
    const uint32_t boff = (uint32_t)(((wc * 64 + (lane & 7)) * PJ_STRIDE
                                      + (lane >> 3) * 8) * 2);

    float acc[4][8][4];
    #pragma unroll
    for (int mi = 0; mi < 4; mi++)
        #pragma unroll
        for (int ni = 0; ni < 8; ni++)
            #pragma unroll
            for (int v = 0; v < 4; v++) acc[mi][ni][v] = 0.0f;

    #pragma unroll
    for (int j = 0; j < 8; j++) {
        int row = (tid + j * 128) >> 3;
        CP_ASYNC16(smb + (uint32_t)(row * PJ_STRIDE + ch_) * 2,
                   g_xh + (size_t)(m0 + row) * NDM + ch_);
        CP_ASYNC16(smb + (uint32_t)(PJ_TILE + row * PJ_STRIDE + ch_) * 2,
                   wt + (size_t)row * NDM + ch_);
    }
    CP_COMMIT;

    for (int s = 0; s < 16; s++) {
        if (s + 1 < 16) {
            const int k1 = (s + 1) * 64;
            const uint32_t sb = (uint32_t)(((s + 1) & 1) * PJ_STAGE);
            #pragma unroll
            for (int j = 0; j < 8; j++) {
                int row = (tid + j * 128) >> 3;
                CP_ASYNC16(smb + (sb + row * PJ_STRIDE + ch_) * 2,
                           g_xh + (size_t)(m0 + row) * NDM + k1 + ch_);
                CP_ASYNC16(smb + (sb + PJ_TILE + row * PJ_STRIDE + ch_) * 2,
                           wt + (size_t)row * NDM + k1 + ch_);
            }
            CP_COMMIT;
            CP_WAIT(1);
        } else {
            CP_WAIT(0);
        }
        __syncthreads();

        const uint32_t Ab = smb + (uint32_t)((s & 1) * PJ_STAGE) * 2 + aoff;
        const uint32_t Bb = smb + (uint32_t)((s & 1) * PJ_STAGE + PJ_TILE) * 2 + boff;

        #pragma unroll
        for (int ks2 = 0; ks2 < 2; ks2++) {
            uint32_t bfr[8][4];
            #pragma unroll
            for (int ni = 0; ni < 8; ni++)
                ldsm_x4(bfr[ni], Bb + (uint32_t)(ni * 8 * PJ_STRIDE * 2 + ks2 * 64));
            #pragma unroll
            for (int ks = 0; ks < 2; ks++) {
                uint32_t af[4][4];
                const uint32_t ka = (uint32_t)((ks2 * 2 + ks) * 32);
                #pragma unroll
                for (int mi = 0; mi < 4; mi++)
                    ldsm_x4(af[mi], Ab + (uint32_t)(mi * 16 * PJ_STRIDE * 2) + ka);
                #pragma unroll
                for (int mi = 0; mi < 4; mi++)
                    #pragma unroll
                    for (int ni = 0; ni < 8; ni++)
                        mma_f16(acc[mi][ni], af[mi], bfr[ni] + 2 * ks);
            }
        }
        __syncthreads();
    }

    const float QSC = 0.125f * 1.44269504088896340736f;
    const int b     = m0 >> 11;
    const int tbase = m0 & 2047;

    if (z < 2) {
        #pragma unroll
        for (int mi = 0; mi < 4; mi++) {
            const int t0 = tbase + wr * 64 + mi * 16 + qr;
            #pragma unroll
            for (int ni = 0; ni < 8; ni++) {
                const int ncta = wc * 64 + ni * 8 + 2 * qc;
                const int ng   = n0 + ncta;
                const int h    = ng >> 6;
                const int d    = ng & 63;
                const size_t bh = (size_t)(b * NH + h);
                if (z == 0) {
                    *(__half2*)&g_qh[(bh * NT + t0) * NDK + d] =
                        __floats2half2_rn(acc[mi][ni][0] * QSC, acc[mi][ni][1] * QSC);
                    *(__half2*)&g_qh[(bh * NT + t0 + 8) * NDK + d] =
                        __floats2half2_rn(acc[mi][ni][2] * QSC, acc[mi][ni][3] * QSC);
                } else {
                    *(__half2*)&g_kh[(bh * NT + t0) * NDK + d] =
                        __floats2half2_rn(acc[mi][ni][0], acc[mi][ni][1]);
                    *(__half2*)&g_kh[(bh * NT + t0 + 8) * NDK + d] =
                        __floats2half2_rn(acc[mi][ni][2], acc[mi][ni][3]);
                }
            }
        }
    } else {
        #pragma unroll
        for (int mi = 0; mi < 4; mi++) {
            const int tl = wr * 64 + mi * 16 + qr;
            #pragma unroll
            for (int ni = 0; ni < 8; ni++) {
                const int dl = wc * 64 + ni * 8 + 2 * qc;
                smh[(dl    ) * VST + tl    ] = __float2half_rn(acc[mi][ni][0]);
                smh[(dl + 1) * VST + tl    ] = __float2half_rn(acc[mi][ni][1]);
                smh[(dl    ) * VST + tl + 8] = __float2half_rn(acc[mi][ni][2]);
                smh[(dl + 1) * VST + tl + 8] = __float2half_rn(acc[mi][ni][3]);
            }
        }
        __syncthreads();
        const int cr = tid >> 4;
        const int cc = (tid & 15) * 8;
        #pragma unroll
        for (int j = 0; j < 16; j++) {
            const int r  = cr + j * 8;
            const int ng = n0 + r;
            const int h  = ng >> 6;
            const int d  = ng & 63;
            __half* dst = g_vt + ((size_t)(b * NH + h) * NDK + d) * NT + tbase + cc;
            *(float4*)dst = *(const float4*)&smh[r * VST + cc];
        }
    }
}

// ---------------------------------------------------------------------------
// Flash attention v6: round-12 base (64-q CTA, 4 warps, occ 3) + PV skewed
// one tile behind S, so PV-mma(kt-1) issues while softmax(kt) waits on S(kt).
// Triple buffering makes V(kt-1) exactly safe vs the tile-(kt+2) overwrite.
// ---------------------------------------------------------------------------
#define AT_STRIDE 72
#define AT_TILEH  (64 * AT_STRIDE)
#define AT_KOFF   (64 * AT_STRIDE)
#define AT_VOFF   (AT_KOFF + 3 * AT_TILEH)
#define AT_SMEM   ((AT_VOFF + 3 * AT_TILEH) * 2)   // 64512 B

__global__ __launch_bounds__(128, 3) void attn_h(float* __restrict__ out)
{
    extern __shared__ __half smh[];
    const uint32_t smb = smem_u32(smh);

    const int qt = 31 - (int)blockIdx.x;
    const int bh = blockIdx.y;
    const int b  = bh >> 4;
    const int h  = bh & 15;
    const int q0 = qt * 64;

    const __half* qg = g_qh + (size_t)bh * NT * NDK;
    const __half* kg = g_kh + (size_t)bh * NT * NDK;
    const __half* vg = g_vt + (size_t)bh * NDK * NT;

    const int tid  = threadIdx.x;
    const int wid  = tid >> 5;
    const int lane = tid & 31;
    const int qr   = lane >> 2;
    const int qc   = lane & 3;

    const int ch_   = (tid & 7) * 8;
    const int krow_ = tid >> 3;

    const uint32_t lmoff = (uint32_t)(((lane & 7) * AT_STRIDE + (lane >> 3) * 8) * 2);

    #pragma unroll
    for (int j = 0; j < 4; j++) {
        int row = krow_ + j * 16;
        CP_ASYNC16(smb + (uint32_t)(row * AT_STRIDE + ch_) * 2,
                   qg + (size_t)(q0 + row) * NDK + ch_);
    }
    CP_COMMIT;

    #pragma unroll
    for (int j = 0; j < 4; j++) {
        int row = krow_ + j * 16;
        CP_ASYNC16(smb + (uint32_t)(AT_KOFF + row * AT_STRIDE + ch_) * 2,
                   kg + (size_t)row * NDK + ch_);
        CP_ASYNC16(smb + (uint32_t)(AT_VOFF + row * AT_STRIDE + ch_) * 2,
                   vg + (size_t)row * NT + ch_);
    }
    CP_COMMIT;

    CP_WAIT(1);
    __syncthreads();

    uint32_t qf[4][4];
    {
        const __half* Qw = smh + (wid * 16) * AT_STRIDE;
        #pragma unroll
        for (int ks = 0; ks < 4; ks++) {
            const __half* p = Qw + qr * AT_STRIDE + ks * 16 + 2 * qc;
            qf[ks][0] = *(const uint32_t*)(p);
            qf[ks][1] = *(const uint32_t*)(p + 8 * AT_STRIDE);
            qf[ks][2] = *(const uint32_t*)(p + 8);
            qf[ks][3] = *(const uint32_t*)(p + 8 * AT_STRIDE + 8);
        }
    }

    float o[8][4];
    #pragma unroll
    for (int ni = 0; ni < 8; ni++)
        #pragma unroll
        for (int v = 0; v < 4; v++) o[ni][v] = 0.0f;
    float lsum[4] = {0.0f, 0.0f, 0.0f, 0.0f};
    float m0 = -INFINITY, m1 = -INFINITY;

    // pipeline-carried state: pf + alphas of the PREVIOUS tile
    uint32_t pfp[4][4];
    float aP0 = 1.0f, aP1 = 1.0f;

    const uint32_t bones[2] = {0x3C003C00u, 0x3C003C00u};
    const int ntiles = qt + 1;

    int cur = 0, nxt = 1, pvb = 0;
    for (int kt = 0; kt < ntiles; kt++) {
        if (kt + 1 < ntiles) {
            const int s1 = (kt + 1) * 64;
            const uint32_t kb = AT_KOFF + (uint32_t)(nxt * AT_TILEH);
            const uint32_t vb = AT_VOFF + (uint32_t)(nxt * AT_TILEH);
            #pragma unroll
            for (int j = 0; j < 4; j++) {
                int row = krow_ + j * 16;
                CP_ASYNC16(smb + (kb + row * AT_STRIDE + ch_) * 2,
                           kg + (size_t)(s1 + row) * NDK + ch_);
                CP_ASYNC16(smb + (vb + row * AT_STRIDE + ch_) * 2,
                           vg + (size_t)row * NT + s1 + ch_);
            }
            CP_COMMIT;
            CP_WAIT(1);
        } else {
            CP_WAIT(0);
        }
        __syncthreads();

        const uint32_t Kb = smb + (AT_KOFF + cur * AT_TILEH) * 2 + lmoff;
        const int s0 = kt * 64;

        // ---- S(kt) mma ----
        float sc[8][4];
        #pragma unroll
        for (int ni = 0; ni < 8; ni++)
            #pragma unroll
            for (int v = 0; v < 4; v++) sc[ni][v] = 0.0f;

        #pragma unroll
        for (int ni = 0; ni < 8; ni++) {
            const uint32_t base = Kb + (uint32_t)(ni * 8 * AT_STRIDE * 2);
            uint32_t kf[4];
            ldsm_x4(kf, base);
            mma_f16(sc[ni], qf[0], kf);
            mma_f16(sc[ni], qf[1], kf + 2);
            ldsm_x4(kf, base + 64);
            mma_f16(sc[ni], qf[2], kf);
            mma_f16(sc[ni], qf[3], kf + 2);
        }

        // ---- deferred PV(kt-1): independent of softmax(kt); covers S latency ----
        if (kt > 0) {
            const uint32_t Vp = smb + (AT_VOFF + pvb * AT_TILEH) * 2 + lmoff;
            #pragma unroll
            for (int ni = 0; ni < 8; ni++) {
                o[ni][0] *= aP0; o[ni][1] *= aP0;
                o[ni][2] *= aP1; o[ni][3] *= aP1;
            }
            #pragma unroll
            for (int ni = 0; ni < 8; ni++) {
                const uint32_t base = Vp + (uint32_t)(ni * 8 * AT_STRIDE * 2);
                uint32_t vf[4];
                ldsm_x4(vf, base);
                mma_f16(o[ni], pfp[0], vf);
                mma_f16(o[ni], pfp[1], vf + 2);
                ldsm_x4(vf, base + 64);
                mma_f16(o[ni], pfp[2], vf);
                mma_f16(o[ni], pfp[3], vf + 2);
            }
        }

        // ---- causal mask (diagonal tile only) ----
        if (kt == qt) {
            const int r0g = q0 + wid * 16 + qr;
            const int r1g = r0g + 8;
            #pragma unroll
            for (int ni = 0; ni < 8; ni++) {
                const int c = s0 + ni * 8 + 2 * qc;
                if (c     > r0g) sc[ni][0] = -INFINITY;
                if (c + 1 > r0g) sc[ni][1] = -INFINITY;
                if (c     > r1g) sc[ni][2] = -INFINITY;
                if (c + 1 > r1g) sc[ni][3] = -INFINITY;
            }
        }

        // ---- softmax(kt) ----
        float rmax0 = sc[0][0], rmax1 = sc[0][2];
        #pragma unroll
        for (int ni = 0; ni < 8; ni++) {
            rmax0 = fmaxf(rmax0, fmaxf(sc[ni][0], sc[ni][1]));
            rmax1 = fmaxf(rmax1, fmaxf(sc[ni][2], sc[ni][3]));
        }
        rmax0 = fmaxf(rmax0, __shfl_xor_sync(0xffffffffu, rmax0, 1));
        rmax0 = fmaxf(rmax0, __shfl_xor_sync(0xffffffffu, rmax0, 2));
        rmax1 = fmaxf(rmax1, __shfl_xor_sync(0xffffffffu, rmax1, 1));
        rmax1 = fmaxf(rmax1, __shfl_xor_sync(0xffffffffu, rmax1, 2));

        const float mn0 = fmaxf(m0, rmax0);
        const float mn1 = fmaxf(m1, rmax1);
        const float a0  = exp2f(m0 - mn0);
        const float a1  = exp2f(m1 - mn1);
        m0 = mn0;  m1 = mn1;

        #pragma unroll
        for (int ks = 0; ks < 4; ks++) {
            pfp[ks][0] = h2e(sc[2*ks    ][0] - mn0, sc[2*ks    ][1] - mn0);
            pfp[ks][1] = h2e(sc[2*ks    ][2] - mn1, sc[2*ks    ][3] - mn1);
            pfp[ks][2] = h2e(sc[2*ks + 1][0] - mn0, sc[2*ks + 1][1] - mn0);
            pfp[ks][3] = h2e(sc[2*ks + 1][2] - mn1, sc[2*ks + 1][3] - mn1);
        }
        aP0 = a0;  aP1 = a1;

        lsum[0] *= a0;  lsum[2] *= a1;
        mma_f16(lsum, pfp[0], bones);
        mma_f16(lsum, pfp[1], bones);
        mma_f16(lsum, pfp[2], bones);
        mma_f16(lsum, pfp[3], bones);

        pvb = cur;
        cur = nxt;
        nxt = (nxt == 2) ? 0 : nxt + 1;
    }

    // ---- drain: rescale + PV(last) ----
    {
        const uint32_t Vp = smb + (AT_VOFF + pvb * AT_TILEH) * 2 + lmoff;
        #pragma unroll
        for (int ni = 0; ni < 8; ni++) {
            o[ni][0] *= aP0; o[ni][1] *= aP0;
            o[ni][2] *= aP1; o[ni][3] *= aP1;
        }
        #pragma unroll
        for (int ni = 0; ni < 8; ni++) {
            const uint32_t base = Vp + (uint32_t)(ni * 8 * AT_STRIDE * 2);
            uint32_t vf[4];
            ldsm_x4(vf, base);
            mma_f16(o[ni], pfp[0], vf);
            mma_f16(o[ni], pfp[1], vf + 2);
            ldsm_x4(vf, base + 64);
            mma_f16(o[ni], pfp[2], vf);
            mma_f16(o[ni], pfp[3], vf + 2);
        }
    }

    const float inv0 = 1.0f / lsum[0];
    const float inv1 = 1.0f / lsum[2];
    const int t0 = q0 + wid * 16 + qr;
    size_t base0 = ((size_t)b * NT + t0) * (NH * NDK) + h * NDK;
    size_t base1 = base0 + 8 * (size_t)(NH * NDK);
    #pragma unroll
    for (int ni = 0; ni < 8; ni++) {
        const int n = ni * 8 + 2 * qc;
        *(float2*)&out[base0 + n] = make_float2(o[ni][0] * inv0, o[ni][1] * inv0);
        *(float2*)&out[base1 + n] = make_float2(o[ni][2] * inv1, o[ni][3] * inv1);
    }
}

// ---------------------------------------------------------------------------
extern "C" void kernel_launch(void* const* d_in, const int* in_sizes, int n_in,
                              void* d_out, int out_size)
{
    (void)in_sizes; (void)n_in; (void)out_size;
    const float* x  = (const float*)d_in[0];
    const float* Wq = (const float*)d_in[1];
    const float* Wk = (const float*)d_in[2];
    const float* Wv = (const float*)d_in[3];
    float* out = (float*)d_out;

    cudaFuncSetAttribute(proj_h,
                         cudaFuncAttributeMaxDynamicSharedMemorySize, PJ_SMEM);
    cudaFuncSetAttribute(attn_h,
                         cudaFuncAttributeMaxDynamicSharedMemorySize, AT_SMEM);

    convert_x<<<NB * NT * NDM / 1024, 256>>>(x);
    convert_w<<<dim3(NDM / 32, NDK / 32, 48), dim3(32, 8)>>>(Wq, Wk, Wv);

    proj_h<<<dim3(NB * NT / 128, 24), 128, PJ_SMEM>>>();

    attn_h<<<dim3(NT / 64, NB * NH), 128, AT_SMEM>>>(out);
}

// round 16
// speedup vs baseline: 1.0306x; 1.0306x over previous
#include <cuda_runtime.h>
#include <cuda_fp16.h>
#include <math.h>
#include <stdint.h>

#define NB 4
#define NT 2048
#define NDM 1024
#define NH 16
#define NDK 64

// fp16 staging buffers
__device__ __half g_xh[NB*NT*NDM];        // x in fp16            [b*t][d]
__device__ __half g_wth[3*NH*NDK*NDM];    // W fp16 transposed    [z*1024+n][d]
__device__ __half g_qh[NB*NH*NT*NDK];     // Q*0.125*log2e fp16   [bh][t][d]
__device__ __half g_kh[NB*NH*NT*NDK];     // K fp16               [bh][t][d]
__device__ __half g_vt[NB*NH*NDK*NT];     // V fp16 TRANSPOSED    [bh][d][t]

__device__ __forceinline__ void mma_f16(float* c, const uint32_t* a, const uint32_t* b) {
    asm volatile("mma.sync.aligned.m16n8k16.row.col.f32.f16.f16.f32 "
                 "{%0,%1,%2,%3}, {%4,%5,%6,%7}, {%8,%9}, {%0,%1,%2,%3};"
                 : "+f"(c[0]), "+f"(c[1]), "+f"(c[2]), "+f"(c[3])
                 : "r"(a[0]), "r"(a[1]), "r"(a[2]), "r"(a[3]),
                   "r"(b[0]), "r"(b[1]));
}
__device__ __forceinline__ void ldsm_x4(uint32_t* d, uint32_t addr) {
    asm volatile("ldmatrix.sync.aligned.m8n8.x4.shared.b16 {%0,%1,%2,%3}, [%4];"
                 : "=r"(d[0]), "=r"(d[1]), "=r"(d[2]), "=r"(d[3]) : "r"(addr));
}
__device__ __forceinline__ uint32_t smem_u32(const void* p) {
    uint32_t a;
    asm("{ .reg .u64 t; cvta.to.shared.u64 t, %1; cvt.u32.u64 %0, t; }"
        : "=r"(a) : "l"(p));
    return a;
}
__device__ __forceinline__ uint32_t h2e(float lo, float hi) {
    __half2 h = h2exp2(__floats2half2_rn(lo, hi));
    return *(uint32_t*)&h;
}
#define CP_ASYNC16(dst, src) \
    asm volatile("cp.async.cg.shared.global [%0], [%1], 16;" \
                 :: "r"(dst), "l"(src) : "memory")
#define CP_COMMIT  asm volatile("cp.async.commit_group;" ::: "memory")
#define CP_WAIT(n) asm volatile("cp.async.wait_group %0;" :: "n"(n) : "memory")

// ---------------------------------------------------------------------------
// Pre-pass 1: x -> fp16
// ---------------------------------------------------------------------------
__global__ __launch_bounds__(256) void convert_x(const float* __restrict__ x)
{
    const int i = ((int)blockIdx.x * 256 + (int)threadIdx.x) * 4;
    float4 v = *(const float4*)&x[i];
    *(__half2*)&g_xh[i]     = __floats2half2_rn(v.x, v.y);
    *(__half2*)&g_xh[i + 2] = __floats2half2_rn(v.z, v.w);
}

// ---------------------------------------------------------------------------
// Pre-pass 2: W[h][d][n] -> Wt fp16 [z*1024 + h*64 + n][d]
// ---------------------------------------------------------------------------
__global__ __launch_bounds__(256) void convert_w(
    const float* __restrict__ Wq, const float* __restrict__ Wk,
    const float* __restrict__ Wv)
{
    __shared__ float tile[32][33];
    const int zh = blockIdx.z;
    const int z = zh >> 4, h = zh & 15;
    const float* W = (z == 0 ? Wq : z == 1 ? Wk : Wv) + (size_t)h * NDM * NDK;
    const int d0 = blockIdx.x * 32;
    const int n0 = blockIdx.y * 32;
    const int tx = threadIdx.x, ty = threadIdx.y;

    #pragma unroll
    for (int j = 0; j < 4; j++)
        tile[ty + j * 8][tx] = W[(size_t)(d0 + ty + j * 8) * NDK + n0 + tx];
    __syncthreads();
    __half* dst = g_wth + ((size_t)(z * NH + h) * NDK) * NDM;
    #pragma unroll
    for (int j = 0; j < 4; j++)
        dst[(size_t)(n0 + ty + j * 8) * NDM + d0 + tx] =
            __float2half_rn(tile[tx][ty + j * 8]);
}

// ---------------------------------------------------------------------------
// Projection GEMM v3b: 128 threads, 4 warps (2x2), warp tile 64x64,
// BK=64, TRIPLE-buffered cp.async -> single barrier per stage.
// Smem: 3 stages x 36864 B = 110592 B (2 CTAs/SM = 221184 B).
// ---------------------------------------------------------------------------
#define PJ_STRIDE 72
#define PJ_TILE   (128 * PJ_STRIDE)
#define PJ_STAGE  (2 * PJ_TILE)          // 18432 halves per stage
#define PJ_SMEM   (3 * PJ_STAGE * 2)     // 110592 B
#define VST 136

__global__ __launch_bounds__(128, 2) void proj_h()
{
    extern __shared__ __half smh[];
    const uint32_t smb = smem_u32(smh);

    const int m0 = blockIdx.x * 128;
    const int by = blockIdx.y;
    const int z  = by >> 3;
    const int n0 = (by & 7) * 128;
    const __half* wt = g_wth + (size_t)(z * 1024 + n0) * NDM;

    const int tid  = threadIdx.x;
    const int lane = tid & 31;
    const int qr   = lane >> 2;
    const int qc   = lane & 3;
    const int wid  = tid >> 5;
    const int wr   = wid >> 1;
    const int wc   = wid & 1;

    const int ch_  = (tid & 7) * 8;

    const uint32_t aoff = (uint32_t)(((wr * 64 + (lane & 15)) * PJ_STRIDE
                                      + (lane >> 4) * 8) * 2);
    const uint32_t boff = (uint32_t)(((wc * 64 + (lane & 7)) * PJ_STRIDE
                                      + (lane >> 3) * 8) * 2);

    float acc[4][8][4];
    #pragma unroll
    for (int mi = 0; mi < 4; mi++)
        #pragma unroll
        for (int ni = 0; ni < 8; ni++)
            #pragma unroll
            for (int v = 0; v < 4; v++) acc[mi][ni][v] = 0.0f;

    // prologue: stage 0 into buffer 0
    #pragma unroll
    for (int j = 0; j < 8; j++) {
        int row = (tid + j * 128) >> 3;
        CP_ASYNC16(smb + (uint32_t)(row * PJ_STRIDE + ch_) * 2,
                   g_xh + (size_t)(m0 + row) * NDM + ch_);
        CP_ASYNC16(smb + (uint32_t)(PJ_TILE + row * PJ_STRIDE + ch_) * 2,
                   wt + (size_t)row * NDM + ch_);
    }
    CP_COMMIT;

    int cur = 0, nxt = 1;
    for (int s = 0; s < 16; s++) {
        if (s + 1 < 16) {
            const int k1 = (s + 1) * 64;
            const uint32_t sb = (uint32_t)(nxt * PJ_STAGE);
            #pragma unroll
            for (int j = 0; j < 8; j++) {
                int row = (tid + j * 128) >> 3;
                CP_ASYNC16(smb + (sb + row * PJ_STRIDE + ch_) * 2,
                           g_xh + (size_t)(m0 + row) * NDM + k1 + ch_);
                CP_ASYNC16(smb + (sb + PJ_TILE + row * PJ_STRIDE + ch_) * 2,
                           wt + (size_t)row * NDM + k1 + ch_);
            }
            CP_COMMIT;
            CP_WAIT(1);
        } else {
            CP_WAIT(0);
        }
        __syncthreads();     // single barrier per stage (3-deep buffer)

        const uint32_t Ab = smb + (uint32_t)(cur * PJ_STAGE) * 2 + aoff;
        const uint32_t Bb = smb + (uint32_t)(cur * PJ_STAGE + PJ_TILE) * 2 + boff;

        #pragma unroll
        for (int ks2 = 0; ks2 < 2; ks2++) {
            uint32_t bfr[8][4];
            #pragma unroll
            for (int ni = 0; ni < 8; ni++)
                ldsm_x4(bfr[ni], Bb + (uint32_t)(ni * 8 * PJ_STRIDE * 2 + ks2 * 64));
            #pragma unroll
            for (int ks = 0; ks < 2; ks++) {
                uint32_t af[4][4];
                const uint32_t ka = (uint32_t)((ks2 * 2 + ks) * 32);
                #pragma unroll
                for (int mi = 0; mi < 4; mi++)
                    ldsm_x4(af[mi], Ab + (uint32_t)(mi * 16 * PJ_STRIDE * 2) + ka);
                #pragma unroll
                for (int mi = 0; mi < 4; mi++)
                    #pragma unroll
                    for (int ni = 0; ni < 8; ni++)
                        mma_f16(acc[mi][ni], af[mi], bfr[ni] + 2 * ks);
            }
        }

        cur = nxt;
        nxt = (nxt == 2) ? 0 : nxt + 1;
    }
    __syncthreads();   // before V epilogue reuses smem

    const float QSC = 0.125f * 1.44269504088896340736f;
    const int b     = m0 >> 11;
    const int tbase = m0 & 2047;

    if (z < 2) {
        #pragma unroll
        for (int mi = 0; mi < 4; mi++) {
            const int t0 = tbase + wr * 64 + mi * 16 + qr;
            #pragma unroll
            for (int ni = 0; ni < 8; ni++) {
                const int ncta = wc * 64 + ni * 8 + 2 * qc;
                const int ng   = n0 + ncta;
                const int h    = ng >> 6;
                const int d    = ng & 63;
                const size_t bh = (size_t)(b * NH + h);
                if (z == 0) {
                    *(__half2*)&g_qh[(bh * NT + t0) * NDK + d] =
                        __floats2half2_rn(acc[mi][ni][0] * QSC, acc[mi][ni][1] * QSC);
                    *(__half2*)&g_qh[(bh * NT + t0 + 8) * NDK + d] =
                        __floats2half2_rn(acc[mi][ni][2] * QSC, acc[mi][ni][3] * QSC);
                } else {
                    *(__half2*)&g_kh[(bh * NT + t0) * NDK + d] =
                        __floats2half2_rn(acc[mi][ni][0], acc[mi][ni][1]);
                    *(__half2*)&g_kh[(bh * NT + t0 + 8) * NDK + d] =
                        __floats2half2_rn(acc[mi][ni][2], acc[mi][ni][3]);
                }
            }
        }
    } else {
        #pragma unroll
        for (int mi = 0; mi < 4; mi++) {
            const int tl = wr * 64 + mi * 16 + qr;
            #pragma unroll
            for (int ni = 0; ni < 8; ni++) {
                const int dl = wc * 64 + ni * 8 + 2 * qc;
                smh[(dl    ) * VST + tl    ] = __float2half_rn(acc[mi][ni][0]);
                smh[(dl + 1) * VST + tl    ] = __float2half_rn(acc[mi][ni][1]);
                smh[(dl    ) * VST + tl + 8] = __float2half_rn(acc[mi][ni][2]);
                smh[(dl + 1) * VST + tl + 8] = __float2half_rn(acc[mi][ni][3]);
            }
        }
        __syncthreads();
        const int cr = tid >> 4;
        const int cc = (tid & 15) * 8;
        #pragma unroll
        for (int j = 0; j < 16; j++) {
            const int r  = cr + j * 8;
            const int ng = n0 + r;
            const int h  = ng >> 6;
            const int d  = ng & 63;
            __half* dst = g_vt + ((size_t)(b * NH + h) * NDK + d) * NT + tbase + cc;
            *(float4*)dst = *(const float4*)&smh[r * VST + cc];
        }
    }
}

// ---------------------------------------------------------------------------
// Flash attention (round-12 config verbatim, best measured 134.5us):
// 64-query CTAs (128 threads, 4 warps), occupancy 3. Triple-buffered K/V,
// ones-column row sums, f16x2 exp2.
// ---------------------------------------------------------------------------
#define AT_STRIDE 72
#define AT_TILEH  (64 * AT_STRIDE)
#define AT_KOFF   (64 * AT_STRIDE)
#define AT_VOFF   (AT_KOFF + 3 * AT_TILEH)
#define AT_SMEM   ((AT_VOFF + 3 * AT_TILEH) * 2)   // 64512 B

__global__ __launch_bounds__(128, 3) void attn_h(float* __restrict__ out)
{
    extern __shared__ __half smh[];
    const uint32_t smb = smem_u32(smh);

    const int qt = 31 - (int)blockIdx.x;
    const int bh = blockIdx.y;
    const int b  = bh >> 4;
    const int h  = bh & 15;
    const int q0 = qt * 64;

    const __half* qg = g_qh + (size_t)bh * NT * NDK;
    const __half* kg = g_kh + (size_t)bh * NT * NDK;
    const __half* vg = g_vt + (size_t)bh * NDK * NT;

    const int tid  = threadIdx.x;
    const int wid  = tid >> 5;
    const int lane = tid & 31;
    const int qr   = lane >> 2;
    const int qc   = lane & 3;

    const int ch_   = (tid & 7) * 8;
    const int krow_ = tid >> 3;

    const uint32_t lmoff = (uint32_t)(((lane & 7) * AT_STRIDE + (lane >> 3) * 8) * 2);

    #pragma unroll
    for (int j = 0; j < 4; j++) {
        int row = krow_ + j * 16;
        CP_ASYNC16(smb + (uint32_t)(row * AT_STRIDE + ch_) * 2,
                   qg + (size_t)(q0 + row) * NDK + ch_);
    }
    CP_COMMIT;

    #pragma unroll
    for (int j = 0; j < 4; j++) {
        int row = krow_ + j * 16;
        CP_ASYNC16(smb + (uint32_t)(AT_KOFF + row * AT_STRIDE + ch_) * 2,
                   kg + (size_t)row * NDK + ch_);
        CP_ASYNC16(smb + (uint32_t)(AT_VOFF + row * AT_STRIDE + ch_) * 2,
                   vg + (size_t)row * NT + ch_);
    }
    CP_COMMIT;

    CP_WAIT(1);
    __syncthreads();

    uint32_t qf[4][4];
    {
        const __half* Qw = smh + (wid * 16) * AT_STRIDE;
        #pragma unroll
        for (int ks = 0; ks < 4; ks++) {
            const __half* p = Qw + qr * AT_STRIDE + ks * 16 + 2 * qc;
            qf[ks][0] = *(const uint32_t*)(p);
            qf[ks][1] = *(const uint32_t*)(p + 8 * AT_STRIDE);
            qf[ks][2] = *(const uint32_t*)(p + 8);
            qf[ks][3] = *(const uint32_t*)(p + 8 * AT_STRIDE + 8);
        }
    }

    float o[8][4];
    #pragma unroll
    for (int ni = 0; ni < 8; ni++)
        #pragma unroll
        for (int v = 0; v < 4; v++) o[ni][v] = 0.0f;
    float lsum[4] = {0.0f, 0.0f, 0.0f, 0.0f};
    float m0 = -INFINITY, m1 = -INFINITY;

    const uint32_t bones[2] = {0x3C003C00u, 0x3C003C00u};
    const int ntiles = qt + 1;

    int cur = 0, nxt = 1;
    for (int kt = 0; kt < ntiles; kt++) {
        if (kt + 1 < ntiles) {
            const int s1 = (kt + 1) * 64;
            const uint32_t kb = AT_KOFF + (uint32_t)(nxt * AT_TILEH);
            const uint32_t vb = AT_VOFF + (uint32_t)(nxt * AT_TILEH);
            #pragma unroll
            for (int j = 0; j < 4; j++) {
                int row = krow_ + j * 16;
                CP_ASYNC16(smb + (kb + row * AT_STRIDE + ch_) * 2,
                           kg + (size_t)(s1 + row) * NDK + ch_);
                CP_ASYNC16(smb + (vb + row * AT_STRIDE + ch_) * 2,
                           vg + (size_t)row * NT + s1 + ch_);
            }
            CP_COMMIT;
            CP_WAIT(1);
        } else {
            CP_WAIT(0);
        }
        __syncthreads();

        const uint32_t Kb = smb + (AT_KOFF + cur * AT_TILEH) * 2 + lmoff;
        const uint32_t Vb = smb + (AT_VOFF + cur * AT_TILEH) * 2 + lmoff;
        const int s0 = kt * 64;

        float sc[8][4];
        #pragma unroll
        for (int ni = 0; ni < 8; ni++)
            #pragma unroll
            for (int v = 0; v < 4; v++) sc[ni][v] = 0.0f;

        #pragma unroll
        for (int ni = 0; ni < 8; ni++) {
            const uint32_t base = Kb + (uint32_t)(ni * 8 * AT_STRIDE * 2);
            uint32_t kf[4];
            ldsm_x4(kf, base);
            mma_f16(sc[ni], qf[0], kf);
            mma_f16(sc[ni], qf[1], kf + 2);
            ldsm_x4(kf, base + 64);
            mma_f16(sc[ni], qf[2], kf);
            mma_f16(sc[ni], qf[3], kf + 2);
        }

        if (kt == qt) {
            const int r0g = q0 + wid * 16 + qr;
            const int r1g = r0g + 8;
            #pragma unroll
            for (int ni = 0; ni < 8; ni++) {
                const int c = s0 + ni * 8 + 2 * qc;
                if (c     > r0g) sc[ni][0] = -INFINITY;
                if (c + 1 > r0g) sc[ni][1] = -INFINITY;
                if (c     > r1g) sc[ni][2] = -INFINITY;
                if (c + 1 > r1g) sc[ni][3] = -INFINITY;
            }
        }

        float rmax0 = sc[0][0], rmax1 = sc[0][2];
        #pragma unroll
        for (int ni = 0; ni < 8; ni++) {
            rmax0 = fmaxf(rmax0, fmaxf(sc[ni][0], sc[ni][1]));
            rmax1 = fmaxf(rmax1, fmaxf(sc[ni][2], sc[ni][3]));
        }
        rmax0 = fmaxf(rmax0, __shfl_xor_sync(0xffffffffu, rmax0, 1));
        rmax0 = fmaxf(rmax0, __shfl_xor_sync(0xffffffffu, rmax0, 2));
        rmax1 = fmaxf(rmax1, __shfl_xor_sync(0xffffffffu, rmax1, 1));
        rmax1 = fmaxf(rmax1, __shfl_xor_sync(0xffffffffu, rmax1, 2));

        const float mn0 = fmaxf(m0, rmax0);
        const float mn1 = fmaxf(m1, rmax1);
        const float a0  = exp2f(m0 - mn0);
        const float a1  = exp2f(m1 - mn1);
        m0 = mn0;  m1 = mn1;

        #pragma unroll
        for (int ni = 0; ni < 8; ni++) {
            o[ni][0] *= a0; o[ni][1] *= a0;
            o[ni][2] *= a1; o[ni][3] *= a1;
        }
        lsum[0] *= a0;  lsum[2] *= a1;

        uint32_t pf[4][4];
        #pragma unroll
        for (int ks = 0; ks < 4; ks++) {
            pf[ks][0] = h2e(sc[2*ks    ][0] - mn0, sc[2*ks    ][1] - mn0);
            pf[ks][1] = h2e(sc[2*ks    ][2] - mn1, sc[2*ks    ][3] - mn1);
            pf[ks][2] = h2e(sc[2*ks + 1][0] - mn0, sc[2*ks + 1][1] - mn0);
            pf[ks][3] = h2e(sc[2*ks + 1][2] - mn1, sc[2*ks + 1][3] - mn1);
        }

        mma_f16(lsum, pf[0], bones);
        mma_f16(lsum, pf[1], bones);
        mma_f16(lsum, pf[2], bones);
        mma_f16(lsum, pf[3], bones);

        #pragma unroll
        for (int ni = 0; ni < 8; ni++) {
            const uint32_t base = Vb + (uint32_t)(ni * 8 * AT_STRIDE * 2);
            uint32_t vf[4];
            ldsm_x4(vf, base);
            mma_f16(o[ni], pf[0], vf);
            mma_f16(o[ni], pf[1], vf + 2);
            ldsm_x4(vf, base + 64);
            mma_f16(o[ni], pf[2], vf);
            mma_f16(o[ni], pf[3], vf + 2);
        }

        cur = nxt;
        nxt = (nxt == 2) ? 0 : nxt + 1;
    }

    const float inv0 = 1.0f / lsum[0];
    const float inv1 = 1.0f / lsum[2];
    const int t0 = q0 + wid * 16 + qr;
    size_t base0 = ((size_t)b * NT + t0) * (NH * NDK) + h * NDK;
    size_t base1 = base0 + 8 * (size_t)(NH * NDK);
    #pragma unroll
    for (int ni = 0; ni < 8; ni++) {
        const int n = ni * 8 + 2 * qc;
        *(float2*)&out[base0 + n] = make_float2(o[ni][0] * inv0, o[ni][1] * inv0);
        *(float2*)&out[base1 + n] = make_float2(o[ni][2] * inv1, o[ni][3] * inv1);
    }
}

// ---------------------------------------------------------------------------
extern "C" void kernel_launch(void* const* d_in, const int* in_sizes, int n_in,
                              void* d_out, int out_size)
{
    (void)in_sizes; (void)n_in; (void)out_size;
    const float* x  = (const float*)d_in[0];
    const float* Wq = (const float*)d_in[1];
    const float* Wk = (const float*)d_in[2];
    const float* Wv = (const float*)d_in[3];
    float* out = (float*)d_out;

    cudaFuncSetAttribute(proj_h,
                         cudaFuncAttributeMaxDynamicSharedMemorySize, PJ_SMEM);
    cudaFuncSetAttribute(attn_h,
                         cudaFuncAttributeMaxDynamicSharedMemorySize, AT_SMEM);

    convert_x<<<NB * NT * NDM / 1024, 256>>>(x);
    convert_w<<<dim3(NDM / 32, NDK / 32, 48), dim3(32, 8)>>>(Wq, Wk, Wv);

    proj_h<<<dim3(NB * NT / 128, 24), 128, PJ_SMEM>>>();

    attn_h<<<dim3(NT / 64, NB * NH), 128, AT_SMEM>>>(out);
}